// round 16
// baseline (speedup 1.0000x reference)
#include <cuda_runtime.h>
#include <cstdint>

// Fixed shapes: B=1, N=64, X=256, Y=256, Z=32
#define NINST 64
#define V (256*256*32)                 // 2,097,152 floats / instance
#define CHUNK_VOX 1024                 // voxels per chunk per instance
#define CHUNK_BYTES (CHUNK_VOX*4)      // 4096 B per bulk load (row locality)
#define CHUNK_WORDS 32                 // packed words per chunk per instance
#define NCHUNK (V/CHUNK_VOX)           // 2048 chunks
#define GROUP 8                        // instances per TMA group / half
#define NG 8                           // groups per chunk
#define HALF_BYTES (GROUP*CHUNK_BYTES) // 32 KB per buffer half
#define NTHR 256
#define NBLK 444                       // 148 SMs * 3 resident blocks
#define NSLOT 4                        // partial accumulator slots
#define IMASK 0x000000ffu              // issuing lanes (tid 0..7)

// Dynamic smem layout
#define SM_RAW     0
#define SM_PACKED  (2*HALF_BYTES)                      // 65536
#define SM_MBAR    (SM_PACKED + CHUNK_WORDS*NINST*4)   // 73728
#define SM_CHUNK   (SM_MBAR + 16)                      // 73744
#define SM_TOTAL   73760

// Device state (zero-initialized at load; the last block of every launch
// restores it to zero, so graph replays start clean).
__device__ unsigned g_partial[NSLOT * NINST * NINST];
__device__ unsigned g_ticket;
__device__ unsigned g_done;

// ---------------------------------------------------------------------------
// PTX helpers
// ---------------------------------------------------------------------------
__device__ __forceinline__ unsigned su32(const void* p) {
    return (unsigned)__cvta_generic_to_shared(p);
}
__device__ __forceinline__ void mbar_init(unsigned a, unsigned cnt) {
    asm volatile("mbarrier.init.shared.b64 [%0], %1;" :: "r"(a), "r"(cnt) : "memory");
}
__device__ __forceinline__ void mbar_expect_tx(unsigned a, unsigned tx) {
    asm volatile("mbarrier.arrive.expect_tx.shared.b64 _, [%0], %1;"
                 :: "r"(a), "r"(tx) : "memory");
}
__device__ __forceinline__ void mbar_wait(unsigned a, unsigned parity) {
    asm volatile(
        "{\n\t.reg .pred p;\n\t"
        "WAIT_%=:\n\t"
        "mbarrier.try_wait.parity.acquire.cta.shared::cta.b64 p, [%0], %1, 0x989680;\n\t"
        "@!p bra WAIT_%=;\n\t}"
        :: "r"(a), "r"(parity) : "memory");
}
__device__ __forceinline__ void tma_bulk(unsigned dst, const void* src,
                                         unsigned bytes, unsigned mbar) {
    asm volatile(
        "cp.async.bulk.shared::cta.global.mbarrier::complete_tx::bytes [%0], [%1], %2, [%3];"
        :: "r"(dst), "l"(src), "r"(bytes), "r"(mbar) : "memory");
}
__device__ __forceinline__ void fence_async() {
    asm volatile("fence.proxy.async.shared::cta;" ::: "memory");
}

// ---------------------------------------------------------------------------
// Single fused kernel: champion pipeline with 4KB per-stream TMA slices.
//  - 2 x 32KB halves, 8 groups of 8 instances per 256KB chunk
//  - pack: warp wp owns words [4wp,4wp+4): LDS.128 + 4 ballots per instance
//  - phase B: full 64x64 pair tile (4x4 per thread) over 32 words
// Last block: reduce + exact-integer NMS + state reset.
// ---------------------------------------------------------------------------
extern __shared__ char smem[];

__global__ __launch_bounds__(NTHR) void fused_nms_kernel(
    const float* __restrict__ mask, float* __restrict__ out)
{
    const unsigned sbase = su32(smem);
    unsigned (*packed)[NINST] = (unsigned (*)[NINST])(smem + SM_PACKED);
    volatile int* s_chunk = (volatile int*)(smem + SM_CHUNK);
    const unsigned mb[2] = {sbase + SM_MBAR, sbase + SM_MBAR + 8};

    const int tid  = threadIdx.x;
    const int lane = tid & 31;
    const int wp   = tid >> 5;           // 8 warps

    if (tid == 0) {
        mbar_init(mb[0], 1);
        mbar_init(mb[1], 1);
        fence_async();
    }

    // 16x16 pair-tile map (4x4 instance pairs / thread), bank-conflict free.
    const int ti = ((wp & 1) << 3) + (lane & 7);
    const int tj = ((wp >> 1) << 2) + (lane >> 3);
    const int i0 = ti * 4, j0 = tj * 4;

    unsigned acc[4][4];
#pragma unroll
    for (int r = 0; r < 4; r++)
#pragma unroll
        for (int c2 = 0; c2 < 4; c2++) acc[r][c2] = 0u;

    // Lane jj (tid<8) fires one 4KB bulk for instance g*8+jj into half hb.
    auto lane_issue = [&](int g, int hb, int c) {
        const float* src =
            mask + (size_t)c * CHUNK_VOX + (size_t)(g * GROUP + tid) * V;
        tma_bulk(sbase + SM_RAW + hb * HALF_BYTES + tid * CHUNK_BYTES,
                 src, CHUNK_BYTES, mb[hb]);
    };

    // Prologue: first ticket, then groups 0,1 in flight (8-lane issue).
    if (tid == 0) *s_chunk = (int)atomicAdd(&g_ticket, 1u);
    __syncthreads();
    int c = *s_chunk;
    if (tid < 8 && c < NCHUNK) {
        if (tid == 0) {
            mbar_expect_tx(mb[0], HALF_BYTES);
            mbar_expect_tx(mb[1], HALF_BYTES);
        }
        __syncwarp(IMASK);
        lane_issue(0, 0, c);
        lane_issue(1, 1, c);
    }

    // Pack read address: warp wp owns words [4wp,4wp+4); lane reads 4 voxels.
    const unsigned raw_rd = sbase + SM_RAW + (unsigned)(wp * 512 + lane * 16);
    unsigned ph0 = 0, ph1 = 0;
    int nextc = NCHUNK;   // issuing-lane local (set at g==NG-2)

    while (c < NCHUNK) {
#pragma unroll
        for (int g = 0; g < NG; g++) {
            const int hb = g & 1;
            if (hb == 0) { mbar_wait(mb[0], ph0); ph0 ^= 1; }
            else         { mbar_wait(mb[1], ph1); ph1 ^= 1; }

            // Pack 8 instances (fixed voxel permutation; identical for all
            // instances, so pairwise popcounts are unaffected).
            const unsigned rbase = raw_rd + (unsigned)hb * HALF_BYTES;
#pragma unroll
            for (int jj = 0; jj < GROUP; jj++) {
                uint4 v;
                asm volatile("ld.shared.v4.u32 {%0,%1,%2,%3}, [%4];"
                             : "=r"(v.x), "=r"(v.y), "=r"(v.z), "=r"(v.w)
                             : "r"(rbase + (unsigned)jj * CHUNK_BYTES));
                unsigned b0 = __ballot_sync(0xffffffffu, v.x != 0u);
                unsigned b1 = __ballot_sync(0xffffffffu, v.y != 0u);
                unsigned b2 = __ballot_sync(0xffffffffu, v.z != 0u);
                unsigned b3 = __ballot_sync(0xffffffffu, v.w != 0u);
                if (lane == 0) {
                    const int j = g * GROUP + jj;
                    packed[wp * 4 + 0][j] = b0;
                    packed[wp * 4 + 1][j] = b1;
                    packed[wp * 4 + 2][j] = b2;
                    packed[wp * 4 + 3][j] = b3;
                }
            }
            __syncthreads();  // half hb fully consumed; packed cols visible

            // Refill half hb (8-lane TMA issue).
            if (tid < 8) {
                fence_async();  // order generic LDS reads before async refill
                if (g < NG - 2) {
                    if (tid == 0) mbar_expect_tx(mb[hb], HALF_BYTES);
                    __syncwarp(IMASK);
                    lane_issue(g + 2, hb, c);
                } else if (g == NG - 2) {
                    if (tid == 0) *s_chunk = (int)atomicAdd(&g_ticket, 1u);
                    __syncwarp(IMASK);
                    nextc = *s_chunk;
                    if (nextc < NCHUNK) {
                        if (tid == 0) mbar_expect_tx(mb[0], HALF_BYTES);
                        __syncwarp(IMASK);
                        lane_issue(0, 0, nextc);
                    }
                } else {
                    if (nextc < NCHUNK) {
                        if (tid == 0) mbar_expect_tx(mb[1], HALF_BYTES);
                        __syncwarp(IMASK);
                        lane_issue(1, 1, nextc);
                    }
                }
            }
        }

        // Phase B: full 64x64 accumulation over 32 words (uniform work;
        // overlaps the next chunk's TMA loads already in flight).
#pragma unroll
        for (int w = 0; w < CHUNK_WORDS; w += 2) {
            uint4 A0 = *(const uint4*)&packed[w][i0];
            uint4 B0 = *(const uint4*)&packed[w][j0];
            uint4 A1 = *(const uint4*)&packed[w + 1][i0];
            uint4 B1 = *(const uint4*)&packed[w + 1][j0];
            unsigned a0[4] = {A0.x, A0.y, A0.z, A0.w};
            unsigned b0[4] = {B0.x, B0.y, B0.z, B0.w};
            unsigned a1[4] = {A1.x, A1.y, A1.z, A1.w};
            unsigned b1[4] = {B1.x, B1.y, B1.z, B1.w};
#pragma unroll
            for (int r = 0; r < 4; r++)
#pragma unroll
                for (int c2 = 0; c2 < 4; c2++)
                    acc[r][c2] += __popc(a0[r] & b0[c2]) + __popc(a1[r] & b1[c2]);
        }
        __syncthreads();  // protect packed[] against next chunk's pack writes
        c = *s_chunk;
    }

    // Flush per-block totals (16 atomics / thread, NSLOT-way spread).
    {
        unsigned* gp =
            g_partial + (unsigned)(blockIdx.x & (NSLOT - 1)) * (NINST * NINST);
#pragma unroll
        for (int r = 0; r < 4; r++)
#pragma unroll
            for (int c2 = 0; c2 < 4; c2++)
                atomicAdd(&gp[(i0 + r) * NINST + (j0 + c2)], acc[r][c2]);
    }
    __threadfence();
    __syncthreads();
    if (tid == 0) *s_chunk = (int)atomicAdd(&g_done, 1u);
    __syncthreads();
    if (*s_chunk != NBLK - 1) return;

    // ------------------- Last block: reduce + NMS + reset -------------------
    unsigned* inter = (unsigned*)smem;             // 16 KB (raw area is dead)
    unsigned* ssc   = (unsigned*)(smem + 16384);

    {   // vectorized reduce of NSLOT slots (L1-bypassing loads)
        const uint4* gp4 = (const uint4*)g_partial;   // [NSLOT][1024] uint4
        uint4* in4 = (uint4*)inter;
        for (int e = tid; e < (NINST * NINST) / 4; e += NTHR) {
            uint4 s = make_uint4(0u, 0u, 0u, 0u);
#pragma unroll
            for (int k = 0; k < NSLOT; k++) {
                uint4 v = __ldcg(&gp4[k * (NINST * NINST / 4) + e]);
                s.x += v.x; s.y += v.y; s.z += v.z; s.w += v.w;
            }
            in4[e] = s;
        }
    }
    __syncthreads();

    {   // reset device state for the next replay
        uint4 z = make_uint4(0u, 0u, 0u, 0u);
        uint4* gz = (uint4*)g_partial;
        for (int e = tid; e < (NSLOT * NINST * NINST) / 4; e += NTHR) gz[e] = z;
        if (tid == 0) { g_ticket = 0u; g_done = 0u; }
    }

    if (tid < NINST) ssc[tid] = inter[tid * NINST + tid];  // score = diagonal
    __syncthreads();

    if (tid < 32) {
        const unsigned sj0 = ssc[lane];
        const unsigned sj1 = ssc[lane + 32];
        unsigned long long ind = ~0ULL;

        for (int i = 0; i < NINST; i++) {
            if (!((ind >> i) & 1ULL)) continue;  // warp-uniform
            const unsigned si  = ssc[i];
            const unsigned in0 = inter[i * NINST + lane];
            const unsigned in1 = inter[i * NINST + lane + 32];
            // iou > 0.5 <=> 2*inter > union (exact integers; counts < 2^23)
            const bool h0 = (2u * in0 > si + sj0 - in0);
            const bool h1 = (2u * in1 > si + sj1 - in1);
            unsigned a0 = __ballot_sync(0xffffffffu, h0 && (si > sj0));
            unsigned a1 = __ballot_sync(0xffffffffu, h1 && (si > sj1));
            unsigned c0 = __ballot_sync(0xffffffffu, h0 && (sj0 > si));
            unsigned c1 = __ballot_sync(0xffffffffu, h1 && (sj1 > si));
            unsigned long long A  = ((unsigned long long)a1 << 32) | a0;
            unsigned long long Bm = ((unsigned long long)c1 << 32) | c0;
            if (A) {
                int jb = __ffsll((long long)A) - 1;   // first break j
                unsigned long long before = (1ULL << jb) - 1ULL;
                if (Bm & before) ind &= ~(1ULL << i); // earlier j beat i first
                ind &= ~(1ULL << jb);
            } else if (Bm) {
                ind &= ~(1ULL << i);
            }
        }
        out[lane]      = (float)((ind >> lane) & 1ULL);
        out[lane + 32] = (float)((ind >> (lane + 32)) & 1ULL);
    }
}

// ---------------------------------------------------------------------------
extern "C" void kernel_launch(void* const* d_in, const int* in_sizes, int n_in,
                              void* d_out, int out_size) {
    const float* mask = (const float*)d_in[0];
    static bool attr_done = false;
    if (!attr_done) {  // host-side attrs: first (pre-capture) call sets them
        cudaFuncSetAttribute(fused_nms_kernel,
                             cudaFuncAttributeMaxDynamicSharedMemorySize,
                             SM_TOTAL);
        cudaFuncSetAttribute(fused_nms_kernel,
                             cudaFuncAttributePreferredSharedMemoryCarveout,
                             cudaSharedmemCarveoutMaxShared);
        attr_done = true;
    }
    fused_nms_kernel<<<NBLK, NTHR, SM_TOTAL>>>(mask, (float*)d_out);
}

// round 17
// speedup vs baseline: 1.0365x; 1.0365x over previous
#include <cuda_runtime.h>
#include <cstdint>

// Fixed shapes: B=1, N=64, X=256, Y=256, Z=32
#define NINST 64
#define V (256*256*32)                 // 2,097,152 floats / instance
#define CHUNK_VOX 512                  // voxels per chunk per instance
#define CHUNK_BYTES (CHUNK_VOX*4)      // 2048 B per bulk load
#define CHUNK_WORDS 16                 // packed words per chunk per instance
#define NCHUNK (V/CHUNK_VOX)           // 4096 chunks
#define GROUP 16                       // instances per TMA group / half
#define HALF_BYTES (GROUP*CHUNK_BYTES) // 32 KB per buffer half
#define NTHR 256
#define NBLK 444                       // 148 SMs * 3 resident blocks
#define NSLOT 8                        // partial accumulator slots
#define IMASK 0x0000ffffu              // issuing lanes (tid 0..15)

// Dynamic smem layout
#define SM_RAW     0
#define SM_PACKED  (2*HALF_BYTES)                      // 65536
#define SM_MBAR    (SM_PACKED + CHUNK_WORDS*NINST*4)   // 69632
#define SM_CHUNK   (SM_MBAR + 16)                      // 69648
#define SM_TOTAL   69664

// Device state (zero-initialized at load; the last block of every launch
// restores it to zero, so graph replays start clean).
__device__ unsigned g_partial[NSLOT * NINST * NINST];
__device__ unsigned g_ticket;
__device__ unsigned g_done;

// ---------------------------------------------------------------------------
// PTX helpers
// ---------------------------------------------------------------------------
__device__ __forceinline__ unsigned su32(const void* p) {
    return (unsigned)__cvta_generic_to_shared(p);
}
__device__ __forceinline__ void mbar_init(unsigned a, unsigned cnt) {
    asm volatile("mbarrier.init.shared.b64 [%0], %1;" :: "r"(a), "r"(cnt) : "memory");
}
__device__ __forceinline__ void mbar_expect_tx(unsigned a, unsigned tx) {
    asm volatile("mbarrier.arrive.expect_tx.shared.b64 _, [%0], %1;"
                 :: "r"(a), "r"(tx) : "memory");
}
__device__ __forceinline__ void mbar_wait(unsigned a, unsigned parity) {
    asm volatile(
        "{\n\t.reg .pred p;\n\t"
        "WAIT_%=:\n\t"
        "mbarrier.try_wait.parity.acquire.cta.shared::cta.b64 p, [%0], %1, 0x989680;\n\t"
        "@!p bra WAIT_%=;\n\t}"
        :: "r"(a), "r"(parity) : "memory");
}
__device__ __forceinline__ void tma_bulk(unsigned dst, const void* src,
                                         unsigned bytes, unsigned mbar) {
    asm volatile(
        "cp.async.bulk.shared::cta.global.mbarrier::complete_tx::bytes [%0], [%1], %2, [%3];"
        :: "r"(dst), "l"(src), "r"(bytes), "r"(mbar) : "memory");
}
__device__ __forceinline__ void fence_async() {
    asm volatile("fence.proxy.async.shared::cta;" ::: "memory");
}

// ---------------------------------------------------------------------------
// Single fused kernel: Round-4/15 champion structure (444x256, 2x32KB halves,
// 16-instance groups, full 64x64 phase B, 16-lane TMA issue) with
// latency-batched pack (16 loads hoisted) and phase B (4-word LDS batches).
// Last block: reduce + exact-integer NMS + state reset.
// ---------------------------------------------------------------------------
extern __shared__ char smem[];

__global__ __launch_bounds__(NTHR, 3) void fused_nms_kernel(
    const float* __restrict__ mask, float* __restrict__ out)
{
    const unsigned sbase = su32(smem);
    unsigned (*packed)[NINST] = (unsigned (*)[NINST])(smem + SM_PACKED);
    volatile int* s_chunk = (volatile int*)(smem + SM_CHUNK);
    const unsigned mb[2] = {sbase + SM_MBAR, sbase + SM_MBAR + 8};

    const int tid  = threadIdx.x;
    const int lane = tid & 31;
    const int wp   = tid >> 5;           // 8 warps

    if (tid == 0) {
        mbar_init(mb[0], 1);
        mbar_init(mb[1], 1);
        fence_async();
    }

    // 16x16 pair-tile map (4x4 instance pairs / thread), bank-conflict free.
    const int ti = ((wp & 1) << 3) + (lane & 7);
    const int tj = ((wp >> 1) << 2) + (lane >> 3);
    const int i0 = ti * 4, j0 = tj * 4;

    unsigned acc[4][4];
#pragma unroll
    for (int r = 0; r < 4; r++)
#pragma unroll
        for (int c2 = 0; c2 < 4; c2++) acc[r][c2] = 0u;

    // Lane jj (tid<16) fires one 2KB bulk for instance g*16+jj into half hb.
    auto lane_issue = [&](int g, int hb, int c) {
        const float* src =
            mask + (size_t)c * CHUNK_VOX + (size_t)(g * GROUP + tid) * V;
        tma_bulk(sbase + SM_RAW + hb * HALF_BYTES + tid * CHUNK_BYTES,
                 src, CHUNK_BYTES, mb[hb]);
    };

    // Prologue: first ticket, then groups 0,1 in flight (16-lane issue).
    if (tid == 0) *s_chunk = (int)atomicAdd(&g_ticket, 1u);
    __syncthreads();
    int c = *s_chunk;
    if (tid < 16 && c < NCHUNK) {
        if (tid == 0) {
            mbar_expect_tx(mb[0], HALF_BYTES);
            mbar_expect_tx(mb[1], HALF_BYTES);
        }
        __syncwarp(IMASK);
        lane_issue(0, 0, c);
        lane_issue(1, 1, c);
    }

    // Pack read address: warp wp owns words 2wp,2wp+1; lane reads 2 voxels.
    const unsigned raw_rd = sbase + SM_RAW + (unsigned)(wp * 64 + lane * 2) * 4u;
    unsigned ph0 = 0, ph1 = 0;
    int nextc = NCHUNK;   // issuing-lane local (set at g==2)

    while (c < NCHUNK) {
#pragma unroll
        for (int g = 0; g < 4; g++) {
            const int hb = g & 1;
            if (hb == 0) { mbar_wait(mb[0], ph0); ph0 ^= 1; }
            else         { mbar_wait(mb[1], ph1); ph1 ^= 1; }

            // Pack 16 instances: hoist ALL 16 LDS.64 first (MLP=16), then
            // run the ballots. Fixed even/odd voxel permutation; identical
            // for all instances, so pairwise popcounts are unaffected.
            const unsigned rbase = raw_rd + (unsigned)hb * HALF_BYTES;
            uint2 v[GROUP];
#pragma unroll
            for (int jj = 0; jj < GROUP; jj++)
                asm volatile("ld.shared.v2.u32 {%0,%1}, [%2];"
                             : "=r"(v[jj].x), "=r"(v[jj].y)
                             : "r"(rbase + (unsigned)jj * CHUNK_BYTES));
#pragma unroll
            for (int jj = 0; jj < GROUP; jj++) {
                unsigned b0 = __ballot_sync(0xffffffffu, v[jj].x != 0u);
                unsigned b1 = __ballot_sync(0xffffffffu, v[jj].y != 0u);
                if (lane == 0) {
                    const int j = g * GROUP + jj;
                    packed[wp * 2][j]     = b0;
                    packed[wp * 2 + 1][j] = b1;
                }
            }
            __syncthreads();  // half hb fully consumed; packed cols visible

            // Refill half hb (16-lane TMA issue).
            if (tid < 16) {
                fence_async();  // order generic LDS reads before async refill
                if (g == 0) {
                    if (tid == 0) mbar_expect_tx(mb[0], HALF_BYTES);
                    __syncwarp(IMASK);
                    lane_issue(2, 0, c);
                } else if (g == 1) {
                    if (tid == 0) mbar_expect_tx(mb[1], HALF_BYTES);
                    __syncwarp(IMASK);
                    lane_issue(3, 1, c);
                } else if (g == 2) {
                    if (tid == 0) *s_chunk = (int)atomicAdd(&g_ticket, 1u);
                    __syncwarp(IMASK);
                    nextc = *s_chunk;
                    if (nextc < NCHUNK) {
                        if (tid == 0) mbar_expect_tx(mb[0], HALF_BYTES);
                        __syncwarp(IMASK);
                        lane_issue(0, 0, nextc);
                    }
                } else {
                    if (nextc < NCHUNK) {
                        if (tid == 0) mbar_expect_tx(mb[1], HALF_BYTES);
                        __syncwarp(IMASK);
                        lane_issue(1, 1, nextc);
                    }
                }
            }
        }

        // Phase B: full 64x64 accumulation, 4-word LDS batches (8 LDS.128
        // issued back-to-back -> exposed smem latency halves). Overlaps the
        // next chunk's TMA loads already in flight.
#pragma unroll
        for (int w = 0; w < CHUNK_WORDS; w += 4) {
            uint4 A0 = *(const uint4*)&packed[w][i0];
            uint4 B0 = *(const uint4*)&packed[w][j0];
            uint4 A1 = *(const uint4*)&packed[w + 1][i0];
            uint4 B1 = *(const uint4*)&packed[w + 1][j0];
            uint4 A2 = *(const uint4*)&packed[w + 2][i0];
            uint4 B2 = *(const uint4*)&packed[w + 2][j0];
            uint4 A3 = *(const uint4*)&packed[w + 3][i0];
            uint4 B3 = *(const uint4*)&packed[w + 3][j0];
            unsigned a0[4] = {A0.x, A0.y, A0.z, A0.w};
            unsigned b0[4] = {B0.x, B0.y, B0.z, B0.w};
            unsigned a1[4] = {A1.x, A1.y, A1.z, A1.w};
            unsigned b1[4] = {B1.x, B1.y, B1.z, B1.w};
            unsigned a2[4] = {A2.x, A2.y, A2.z, A2.w};
            unsigned b2[4] = {B2.x, B2.y, B2.z, B2.w};
            unsigned a3[4] = {A3.x, A3.y, A3.z, A3.w};
            unsigned b3[4] = {B3.x, B3.y, B3.z, B3.w};
#pragma unroll
            for (int r = 0; r < 4; r++)
#pragma unroll
                for (int c2 = 0; c2 < 4; c2++)
                    acc[r][c2] += __popc(a0[r] & b0[c2]) + __popc(a1[r] & b1[c2])
                                + __popc(a2[r] & b2[c2]) + __popc(a3[r] & b3[c2]);
        }
        __syncthreads();  // protect packed[] against next chunk's pack writes
        c = *s_chunk;
    }

    // Flush per-block totals (16 atomics / thread, NSLOT-way spread).
    {
        unsigned* gp =
            g_partial + (unsigned)(blockIdx.x & (NSLOT - 1)) * (NINST * NINST);
#pragma unroll
        for (int r = 0; r < 4; r++)
#pragma unroll
            for (int c2 = 0; c2 < 4; c2++)
                atomicAdd(&gp[(i0 + r) * NINST + (j0 + c2)], acc[r][c2]);
    }
    __threadfence();
    __syncthreads();
    if (tid == 0) *s_chunk = (int)atomicAdd(&g_done, 1u);
    __syncthreads();
    if (*s_chunk != NBLK - 1) return;

    // ------------------- Last block: reduce + NMS + reset -------------------
    unsigned* inter = (unsigned*)smem;             // 16 KB (raw area is dead)
    unsigned* ssc   = (unsigned*)(smem + 16384);

    {   // vectorized reduce of NSLOT slots (L1-bypassing loads)
        const uint4* gp4 = (const uint4*)g_partial;   // [NSLOT][1024] uint4
        uint4* in4 = (uint4*)inter;
        for (int e = tid; e < (NINST * NINST) / 4; e += NTHR) {
            uint4 s = make_uint4(0u, 0u, 0u, 0u);
#pragma unroll
            for (int k = 0; k < NSLOT; k++) {
                uint4 w = __ldcg(&gp4[k * (NINST * NINST / 4) + e]);
                s.x += w.x; s.y += w.y; s.z += w.z; s.w += w.w;
            }
            in4[e] = s;
        }
    }
    __syncthreads();

    {   // reset device state for the next replay
        uint4 z = make_uint4(0u, 0u, 0u, 0u);
        uint4* gz = (uint4*)g_partial;
        for (int e = tid; e < (NSLOT * NINST * NINST) / 4; e += NTHR) gz[e] = z;
        if (tid == 0) { g_ticket = 0u; g_done = 0u; }
    }

    if (tid < NINST) ssc[tid] = inter[tid * NINST + tid];  // score = diagonal
    __syncthreads();

    if (tid < 32) {
        const unsigned sj0 = ssc[lane];
        const unsigned sj1 = ssc[lane + 32];
        unsigned long long ind = ~0ULL;

        for (int i = 0; i < NINST; i++) {
            if (!((ind >> i) & 1ULL)) continue;  // warp-uniform
            const unsigned si  = ssc[i];
            const unsigned in0 = inter[i * NINST + lane];
            const unsigned in1 = inter[i * NINST + lane + 32];
            // iou > 0.5 <=> 2*inter > union (exact integers; counts < 2^23)
            const bool h0 = (2u * in0 > si + sj0 - in0);
            const bool h1 = (2u * in1 > si + sj1 - in1);
            unsigned a0 = __ballot_sync(0xffffffffu, h0 && (si > sj0));
            unsigned a1 = __ballot_sync(0xffffffffu, h1 && (si > sj1));
            unsigned c0 = __ballot_sync(0xffffffffu, h0 && (sj0 > si));
            unsigned c1 = __ballot_sync(0xffffffffu, h1 && (sj1 > si));
            unsigned long long A  = ((unsigned long long)a1 << 32) | a0;
            unsigned long long Bm = ((unsigned long long)c1 << 32) | c0;
            if (A) {
                int jb = __ffsll((long long)A) - 1;   // first break j
                unsigned long long before = (1ULL << jb) - 1ULL;
                if (Bm & before) ind &= ~(1ULL << i); // earlier j beat i first
                ind &= ~(1ULL << jb);
            } else if (Bm) {
                ind &= ~(1ULL << i);
            }
        }
        out[lane]      = (float)((ind >> lane) & 1ULL);
        out[lane + 32] = (float)((ind >> (lane + 32)) & 1ULL);
    }
}

// ---------------------------------------------------------------------------
extern "C" void kernel_launch(void* const* d_in, const int* in_sizes, int n_in,
                              void* d_out, int out_size) {
    const float* mask = (const float*)d_in[0];
    static bool attr_done = false;
    if (!attr_done) {  // host-side attrs: first (pre-capture) call sets them
        cudaFuncSetAttribute(fused_nms_kernel,
                             cudaFuncAttributeMaxDynamicSharedMemorySize,
                             SM_TOTAL);
        cudaFuncSetAttribute(fused_nms_kernel,
                             cudaFuncAttributePreferredSharedMemoryCarveout,
                             cudaSharedmemCarveoutMaxShared);
        attr_done = true;
    }
    fused_nms_kernel<<<NBLK, NTHR, SM_TOTAL>>>(mask, (float*)d_out);
}